// round 9
// baseline (speedup 1.0000x reference)
#include <cuda_runtime.h>
#include <cstdint>
#include <cmath>

// ---------------------------------------------------------------------------
// Problem constants
// ---------------------------------------------------------------------------
#define VOCAB     10000
#define NDEM      2
#define EMB       128
#define B_ROWS    16384
#define SRC_COLS  10002
#define NH        16
#define KPAD      10240
#define KSPLIT    16
#define KRANGE    (KPAD / KSPLIT)    // 640
#define KT        64                 // k-columns per pipeline tile
#define NT        (KRANGE / KT)      // 10
#define NG        (KT / 4)           // 16 groups of 4 cols per tile
#define TM        512                // rows per CTA
#define THREADS   256
#define NCTA      ((B_ROWS / TM) * KSPLIT)   // 512
#define ESTRIDE   80                 // table entry stride (64B data + 16B pad)

// Scratch (__device__ globals: allocation-free rule)
__device__ float g_EW1[KPAD * NH];            // [vocab-col][16]
__device__ float g_S[KSPLIT * 17 * B_ROWS];   // 16 partials x (16 sums + count)

// ---------------------------------------------------------------------------
// packed f32x2 helpers
// ---------------------------------------------------------------------------
__device__ __forceinline__ void fma2(unsigned long long& d, unsigned long long a,
                                     unsigned long long b) {
    asm("fma.rn.f32x2 %0, %1, %2, %0;" : "+l"(d) : "l"(a), "l"(b));
}
__device__ __forceinline__ void add2(unsigned long long& d, unsigned long long a) {
    asm("add.rn.f32x2 %0, %0, %1;" : "+l"(d) : "l"(a));
}
__device__ __forceinline__ unsigned long long pack2(float lo, float hi) {
    unsigned long long r;
    asm("mov.b64 %0, {%1, %2};" : "=l"(r) : "r"(__float_as_uint(lo)), "r"(__float_as_uint(hi)));
    return r;
}
__device__ __forceinline__ void unpack2(unsigned long long v, float& lo, float& hi) {
    unsigned a, b;
    asm("mov.b64 {%0, %1}, %2;" : "=r"(a), "=r"(b) : "l"(v));
    lo = __uint_as_float(a); hi = __uint_as_float(b);
}
__device__ __forceinline__ void cp16(void* s, const void* g) {
    unsigned sa = (unsigned)__cvta_generic_to_shared(s);
    asm volatile("cp.async.cg.shared.global [%0], [%1], 16;" :: "r"(sa), "l"(g));
}

// ---------------------------------------------------------------------------
// Kernel 0: g_EW1[c][n] = sum_d embed[c][d] * W1[(2+d)*16+n]   (0 for c>=VOCAB)
// ---------------------------------------------------------------------------
__global__ __launch_bounds__(512) void ew1_kernel(const float* __restrict__ embed,
                                                  const float* __restrict__ W1) {
    __shared__ float sh_emb[32][EMB];
    __shared__ float sh_w1[EMB][NH];
    const int tid = threadIdx.x;
    const int c0  = blockIdx.x * 32;

    for (int i = tid; i < EMB * NH; i += 512)
        sh_w1[i >> 4][i & 15] = W1[NDEM * NH + i];
    for (int i = tid; i < 32 * EMB; i += 512) {
        int r = i >> 7, k = c0 + r;
        sh_emb[r][i & 127] = (k < VOCAB) ? embed[(long long)k * EMB + (i & 127)] : 0.f;
    }
    __syncthreads();

    const int r = tid >> 4, n = tid & 15, k = c0 + r;
    float a0 = 0.f, a1 = 0.f;
    #pragma unroll 16
    for (int d = 0; d < EMB; d += 2) {
        a0 += sh_emb[r][d]     * sh_w1[d][n];
        a1 += sh_emb[r][d + 1] * sh_w1[d + 1][n];
    }
    g_EW1[k * NH + n] = (k < VOCAB) ? (a0 + a1) : 0.f;
}

// ---------------------------------------------------------------------------
// Kernel 1: partial S = mask_tile @ EW1  via 4-bit subset-sum table.
//   Ballot layout: tile col k -> word (k&1), bit (k>>1).
//   Group g covers cols 4g..4g+3; nibble m bits: 0<->4g, 1<->4g+2, 2<->4g+1, 3<->4g+3.
//   Ballots for staged loads are delayed TWO batches (DRAM-latency cover).
// ---------------------------------------------------------------------------
__global__ __launch_bounds__(THREADS, 3) void pool_kernel(const float* __restrict__ src) {
    __shared__ __align__(16) float    sh_tbl[NG * 16 * ESTRIDE / 4];  // 20 KB
    __shared__ __align__(16) float    sh_e[2][KT * NH];               // 2 x 4 KB
    __shared__ __align__(8)  unsigned sh_bits[2][TM][2];              // 2 x 4 KB

    const int tid  = threadIdx.x;
    const int w    = tid >> 5;
    const int lane = tid & 31;
    const int mtile = blockIdx.x >> 4;
    const int part  = blockIdx.x & (KSPLIT - 1);
    const int row0  = mtile * TM;
    const int kbase = part * KRANGE;
    const float* sb = src + (long long)row0 * SRC_COLS + NDEM;
    const int cl = 2 * lane;
    const unsigned tbl = (unsigned)__cvta_generic_to_shared(&sh_tbl[0]);

    // ---------------- prologue: stage tile 0 ----------------
    cp16(&sh_e[0][tid * 4], g_EW1 + kbase * NH + tid * 4);
    asm volatile("cp.async.commit_group;");
    {
        const int c = kbase + cl;
        #pragma unroll 4
        for (int b = 0; b < 16; ++b) {
            float2 v[4];
            #pragma unroll
            for (int j = 0; j < 4; ++j) {
                int row = 64 * w + 4 * b + j;
                v[j] = (c < VOCAB)
                     ? __ldcs(reinterpret_cast<const float2*>(sb + (long long)row * SRC_COLS + c))
                     : make_float2(0.f, 0.f);
            }
            #pragma unroll
            for (int j = 0; j < 4; ++j) {
                unsigned w0 = __ballot_sync(0xffffffffu, v[j].x != 0.f);
                unsigned w1 = __ballot_sync(0xffffffffu, v[j].y != 0.f);
                if (lane == 0)
                    *reinterpret_cast<uint2*>(&sh_bits[0][64 * w + 4 * b + j][0]) = make_uint2(w0, w1);
            }
        }
    }
    asm volatile("cp.async.wait_group 0;" ::: "memory");
    __syncthreads();

    unsigned long long acc[2][8];
    #pragma unroll
    for (int r = 0; r < 2; ++r)
        #pragma unroll
        for (int i = 0; i < 8; ++i) acc[r][i] = 0ull;
    int cnt0 = 0, cnt1 = 0;

    // build masks for this thread's table item (g = tid>>4, m = tid&15)
    const int bg = tid >> 4, bm = tid & 15;
    const unsigned long long q0 = pack2((bm & 1) ? 1.f : 0.f, (bm & 1) ? 1.f : 0.f);  // e[4g]
    const unsigned long long q1 = pack2((bm & 2) ? 1.f : 0.f, (bm & 2) ? 1.f : 0.f);  // e[4g+2]
    const unsigned long long q2 = pack2((bm & 4) ? 1.f : 0.f, (bm & 4) ? 1.f : 0.f);  // e[4g+1]
    const unsigned long long q3 = pack2((bm & 8) ? 1.f : 0.f, (bm & 8) ? 1.f : 0.f);  // e[4g+3]
    const unsigned tdst = tbl + (bg * 16 + bm) * ESTRIDE;

    // ---------------- main loop over tiles ----------------
    for (int t = 0; t < NT; ++t) {
        const int buf = t & 1, nbuf = buf ^ 1;

        // ---- build subset-sum table from sh_e[buf] ----
        {
            const unsigned eb = (unsigned)__cvta_generic_to_shared(&sh_e[buf][0]) + bg * 4 * 64;
            #pragma unroll
            for (int i = 0; i < 8; ++i) {
                unsigned long long e0, e1, e2, e3, s = 0ull;
                asm("ld.shared.b64 %0, [%1];"     : "=l"(e0) : "r"(eb + i * 8));
                asm("ld.shared.b64 %0, [%1+64];"  : "=l"(e1) : "r"(eb + i * 8));
                asm("ld.shared.b64 %0, [%1+128];" : "=l"(e2) : "r"(eb + i * 8));
                asm("ld.shared.b64 %0, [%1+192];" : "=l"(e3) : "r"(eb + i * 8));
                fma2(s, e0, q0);   // k=4g
                fma2(s, e2, q1);   // k=4g+2
                fma2(s, e1, q2);   // k=4g+1
                fma2(s, e3, q3);   // k=4g+3
                asm volatile("st.shared.b64 [%0], %1;" :: "r"(tdst + i * 8), "l"(s));
            }
        }
        __syncthreads();   // table ready

        const uint2 bw0 = *reinterpret_cast<const uint2*>(&sh_bits[buf][2 * tid][0]);
        const uint2 bw1 = *reinterpret_cast<const uint2*>(&sh_bits[buf][2 * tid + 1][0]);
        cnt0 += __popc(bw0.x) + __popc(bw0.y);
        cnt1 += __popc(bw1.x) + __popc(bw1.y);

        const bool stg = (t + 1 < NT);
        const int cnx = kbase + (t + 1) * KT + cl;
        if (stg) {
            cp16(&sh_e[nbuf][tid * 4], g_EW1 + (kbase + (t + 1) * KT) * NH + tid * 4);
            asm volatile("cp.async.commit_group;");
        }

        // delayed-ballot ring: v0 = batch g-2 (oldest), v1 = batch g-1
        float2 v0[4], v1[4];
        if (stg) {
            #pragma unroll
            for (int j = 0; j < 4; ++j) {
                int row = 64 * w + j;
                v0[j] = (cnx < VOCAB)
                      ? __ldcs(reinterpret_cast<const float2*>(sb + (long long)row * SRC_COLS + cnx))
                      : make_float2(0.f, 0.f);
            }
            #pragma unroll
            for (int j = 0; j < 4; ++j) {
                int row = 64 * w + 4 + j;
                v1[j] = (cnx < VOCAB)
                      ? __ldcs(reinterpret_cast<const float2*>(sb + (long long)row * SRC_COLS + cnx))
                      : make_float2(0.f, 0.f);
            }
        }

        #pragma unroll
        for (int g = 0; g < NG; ++g) {
            // 1) issue loads for batch g+2
            float2 vt[4];
            if (stg && g + 2 < 16) {
                #pragma unroll
                for (int j = 0; j < 4; ++j) {
                    int row = 64 * w + 4 * (g + 2) + j;
                    vt[j] = (cnx < VOCAB)
                          ? __ldcs(reinterpret_cast<const float2*>(sb + (long long)row * SRC_COLS + cnx))
                          : make_float2(0.f, 0.f);
                }
            }
            // 2) consume group g: table lookup + 8 add2 per row
            {
                const unsigned m0 = ((bw0.x >> (2 * g)) & 3u) | (((bw0.y >> (2 * g)) & 3u) << 2);
                const unsigned m1 = ((bw1.x >> (2 * g)) & 3u) | (((bw1.y >> (2 * g)) & 3u) << 2);
                const unsigned a0 = tbl + (g * 16 + m0) * ESTRIDE;
                const unsigned a1 = tbl + (g * 16 + m1) * ESTRIDE;
                unsigned long long e0, e1, e2, e3;
                asm("ld.shared.v2.b64 {%0,%1}, [%2];"    : "=l"(e0), "=l"(e1) : "r"(a0));
                asm("ld.shared.v2.b64 {%0,%1}, [%2+16];" : "=l"(e2), "=l"(e3) : "r"(a0));
                add2(acc[0][0], e0); add2(acc[0][1], e1);
                add2(acc[0][2], e2); add2(acc[0][3], e3);
                asm("ld.shared.v2.b64 {%0,%1}, [%2+32];" : "=l"(e0), "=l"(e1) : "r"(a0));
                asm("ld.shared.v2.b64 {%0,%1}, [%2+48];" : "=l"(e2), "=l"(e3) : "r"(a0));
                add2(acc[0][4], e0); add2(acc[0][5], e1);
                add2(acc[0][6], e2); add2(acc[0][7], e3);
                asm("ld.shared.v2.b64 {%0,%1}, [%2];"    : "=l"(e0), "=l"(e1) : "r"(a1));
                asm("ld.shared.v2.b64 {%0,%1}, [%2+16];" : "=l"(e2), "=l"(e3) : "r"(a1));
                add2(acc[1][0], e0); add2(acc[1][1], e1);
                add2(acc[1][2], e2); add2(acc[1][3], e3);
                asm("ld.shared.v2.b64 {%0,%1}, [%2+32];" : "=l"(e0), "=l"(e1) : "r"(a1));
                asm("ld.shared.v2.b64 {%0,%1}, [%2+48];" : "=l"(e2), "=l"(e3) : "r"(a1));
                add2(acc[1][4], e0); add2(acc[1][5], e1);
                add2(acc[1][6], e2); add2(acc[1][7], e3);
            }
            // 3) ballot oldest batch (g), rotate
            if (stg) {
                #pragma unroll
                for (int j = 0; j < 4; ++j) {
                    unsigned p0 = __ballot_sync(0xffffffffu, v0[j].x != 0.f);
                    unsigned p1 = __ballot_sync(0xffffffffu, v0[j].y != 0.f);
                    if (lane == 0)
                        *reinterpret_cast<uint2*>(&sh_bits[nbuf][64 * w + 4 * g + j][0]) = make_uint2(p0, p1);
                }
                if (g + 2 < 16) {
                    #pragma unroll
                    for (int j = 0; j < 4; ++j) { v0[j] = v1[j]; v1[j] = vt[j]; }
                } else {
                    #pragma unroll
                    for (int j = 0; j < 4; ++j) v0[j] = v1[j];
                }
            }
        }
        if (stg) asm volatile("cp.async.wait_group 0;" ::: "memory");
        __syncthreads();   // bits[nbuf] + e[nbuf] ready; table reusable
    }

    // ---------------- write partials (column-major) ----------------
    const int rg0 = row0 + 2 * tid, rg1 = rg0 + 1;
    #pragma unroll
    for (int i = 0; i < 8; ++i) {
        float lo, hi;
        unpack2(acc[0][i], lo, hi);
        g_S[(part * 17 + 2 * i + 0) * B_ROWS + rg0] = lo;
        g_S[(part * 17 + 2 * i + 1) * B_ROWS + rg0] = hi;
        unpack2(acc[1][i], lo, hi);
        g_S[(part * 17 + 2 * i + 0) * B_ROWS + rg1] = lo;
        g_S[(part * 17 + 2 * i + 1) * B_ROWS + rg1] = hi;
    }
    g_S[(part * 17 + 16) * B_ROWS + rg0] = (float)cnt0;
    g_S[(part * 17 + 16) * B_ROWS + rg1] = (float)cnt1;
}

// ---------------------------------------------------------------------------
// Kernel 2: reduce K-split partials + MLP epilogue
// ---------------------------------------------------------------------------
__global__ void mlp_kernel(const float* __restrict__ src, const float* __restrict__ W1,
                           const float* __restrict__ b1, const float* __restrict__ W2,
                           const float* __restrict__ b2, float* __restrict__ out) {
    int r = blockIdx.x * blockDim.x + threadIdx.x;
    if (r >= B_ROWS) return;

    float s[17];
    #pragma unroll
    for (int n = 0; n < 17; ++n) s[n] = 0.f;
    #pragma unroll
    for (int p = 0; p < KSPLIT; ++p)
        #pragma unroll
        for (int n = 0; n < 17; ++n)
            s[n] += g_S[(p * 17 + n) * B_ROWS + r];

    const float inv = 1.f / s[16];
    const float d0 = src[(long long)r * SRC_COLS + 0];
    const float d1 = src[(long long)r * SRC_COLS + 1];

    float o0 = b2[0], o1 = b2[1];
    #pragma unroll
    for (int j = 0; j < NH; ++j) {
        float z = d0 * W1[j] + d1 * W1[NH + j] + s[j] * inv + b1[j];
        float h = tanhf(z);
        o0 += h * W2[2 * j + 0];
        o1 += h * W2[2 * j + 1];
    }
    out[2 * r + 0] = o0;
    out[2 * r + 1] = o1;
}

// ---------------------------------------------------------------------------
// Launch
// ---------------------------------------------------------------------------
extern "C" void kernel_launch(void* const* d_in, const int* in_sizes, int n_in,
                              void* d_out, int out_size) {
    int iSrc = 0, iEmb = 1, iW1 = 2, iB1 = 3, iW2 = 4, iB2 = 5;
    for (int i = 0; i < n_in; ++i) {
        int s = in_sizes[i];
        if      (s == B_ROWS * SRC_COLS)  iSrc = i;
        else if (s == VOCAB * EMB)        iEmb = i;
        else if (s == (NDEM + EMB) * NH)  iW1  = i;
        else if (s == NH)                 iB1  = i;
        else if (s == NH * 2)             iW2  = i;
        else if (s == 2)                  iB2  = i;
    }
    const float* src   = (const float*)d_in[iSrc];
    const float* embed = (const float*)d_in[iEmb];
    const float* W1    = (const float*)d_in[iW1];
    const float* b1    = (const float*)d_in[iB1];
    const float* W2    = (const float*)d_in[iW2];
    const float* b2    = (const float*)d_in[iB2];
    float* out = (float*)d_out;

    ew1_kernel<<<KPAD / 32, 512>>>(embed, W1);
    pool_kernel<<<NCTA, THREADS>>>(src);
    mlp_kernel<<<(B_ROWS + 255) / 256, 256>>>(src, W1, b1, W2, b2, out);
}

// round 11
// speedup vs baseline: 1.2552x; 1.2552x over previous
#include <cuda_runtime.h>
#include <cstdint>
#include <cmath>

// ---------------------------------------------------------------------------
// Problem constants
// ---------------------------------------------------------------------------
#define VOCAB     10000
#define NDEM      2
#define EMB       128
#define B_ROWS    16384
#define SRC_COLS  10002
#define NH        16
#define KPAD      10240
#define KSPLIT    16
#define KRANGE    (KPAD / KSPLIT)    // 640
#define KT        64                 // k-columns per pipeline tile
#define NT        (KRANGE / KT)      // 10
#define TM        512                // rows per CTA
#define THREADS   256
#define NCTA      ((B_ROWS / TM) * KSPLIT)   // 512

// Scratch (__device__ globals: allocation-free rule)
__device__ float g_EW1[KPAD * NH];            // [vocab-col][16]
__device__ float g_S[KSPLIT * 17 * B_ROWS];   // 16 partials x (16 sums + count)

// ---------------------------------------------------------------------------
// packed f32x2 helpers
// ---------------------------------------------------------------------------
__device__ __forceinline__ void fma2(unsigned long long& d, unsigned long long a,
                                     unsigned long long b) {
    asm("fma.rn.f32x2 %0, %1, %2, %0;" : "+l"(d) : "l"(a), "l"(b));
}
__device__ __forceinline__ unsigned long long pack2(float lo, float hi) {
    unsigned long long r;
    asm("mov.b64 %0, {%1, %2};" : "=l"(r) : "r"(__float_as_uint(lo)), "r"(__float_as_uint(hi)));
    return r;
}
__device__ __forceinline__ void unpack2(unsigned long long v, float& lo, float& hi) {
    unsigned a, b;
    asm("mov.b64 {%0, %1}, %2;" : "=r"(a), "=r"(b) : "l"(v));
    lo = __uint_as_float(a); hi = __uint_as_float(b);
}
__device__ __forceinline__ void cp16(void* s, const void* g) {
    unsigned sa = (unsigned)__cvta_generic_to_shared(s);
    asm volatile("cp.async.cg.shared.global [%0], [%1], 16;" :: "r"(sa), "l"(g));
}

// ---------------------------------------------------------------------------
// Kernel 0: g_EW1[c][n] = sum_d embed[c][d] * W1[(2+d)*16+n]   (0 for c>=VOCAB)
// ---------------------------------------------------------------------------
__global__ __launch_bounds__(512) void ew1_kernel(const float* __restrict__ embed,
                                                  const float* __restrict__ W1) {
    __shared__ float sh_emb[32][EMB];
    __shared__ float sh_w1[EMB][NH];
    const int tid = threadIdx.x;
    const int c0  = blockIdx.x * 32;

    for (int i = tid; i < EMB * NH; i += 512)
        sh_w1[i >> 4][i & 15] = W1[NDEM * NH + i];
    for (int i = tid; i < 32 * EMB; i += 512) {
        int r = i >> 7, k = c0 + r;
        sh_emb[r][i & 127] = (k < VOCAB) ? embed[(long long)k * EMB + (i & 127)] : 0.f;
    }
    __syncthreads();

    const int r = tid >> 4, n = tid & 15, k = c0 + r;
    float a0 = 0.f, a1 = 0.f;
    #pragma unroll 16
    for (int d = 0; d < EMB; d += 2) {
        a0 += sh_emb[r][d]     * sh_w1[d][n];
        a1 += sh_emb[r][d + 1] * sh_w1[d + 1][n];
    }
    g_EW1[k * NH + n] = (k < VOCAB) ? (a0 + a1) : 0.f;
}

// ---------------------------------------------------------------------------
// Kernel 1: partial S = mask_tile @ EW1  (pipelined bitmask GEMM)
//   Staging (R6-proven): warp w stages rows [64w, 64w+64) via float2 loads +
//   ballots; bit layout: tile col k -> word (k&1), bit (k>>1).
//   Consumption: thread (tr = tid&127, rh = tid>>7) accumulates
//   rows 4tr..4tr+3 x N-columns [8rh, 8rh+8): 2 LDS.v2.b64 + 16 fma2 per k.
//   launch_bounds (256,3): 84-reg budget, ~70 live -> no spills, occ 3.
// ---------------------------------------------------------------------------
__global__ __launch_bounds__(THREADS, 3) void pool_kernel(const float* __restrict__ src) {
    __shared__ __align__(16) float    sh_e[2][KT * NH];     // 2 x 4 KB
    __shared__ __align__(8)  unsigned sh_bits[2][TM][2];    // 2 x 4 KB

    const int tid  = threadIdx.x;
    const int w    = tid >> 5;
    const int lane = tid & 31;
    const int tr   = tid & 127;      // consumption row group: rows 4tr..4tr+3
    const int rh   = tid >> 7;       // consumption N-half: cols 8rh..8rh+7
    const int mtile = blockIdx.x >> 4;
    const int part  = blockIdx.x & (KSPLIT - 1);
    const int row0  = mtile * TM;
    const int kbase = part * KRANGE;
    const float* sb = src + (long long)row0 * SRC_COLS + NDEM;
    const int cl = 2 * lane;                     // lane's col offset in a tile (even)

    // ---------------- prologue: stage tile 0 ----------------
    cp16(&sh_e[0][tid * 4], g_EW1 + kbase * NH + tid * 4);
    asm volatile("cp.async.commit_group;");
    {
        const int c = kbase + cl;
        #pragma unroll 4
        for (int b = 0; b < 16; ++b) {
            float2 v[4];
            #pragma unroll
            for (int j = 0; j < 4; ++j) {
                int row = 64 * w + 4 * b + j;
                v[j] = (c < VOCAB)
                     ? __ldcs(reinterpret_cast<const float2*>(sb + (long long)row * SRC_COLS + c))
                     : make_float2(0.f, 0.f);
            }
            #pragma unroll
            for (int j = 0; j < 4; ++j) {
                unsigned w0 = __ballot_sync(0xffffffffu, v[j].x != 0.f);
                unsigned w1 = __ballot_sync(0xffffffffu, v[j].y != 0.f);
                if (lane == 0)
                    *reinterpret_cast<uint2*>(&sh_bits[0][64 * w + 4 * b + j][0]) = make_uint2(w0, w1);
            }
        }
    }
    asm volatile("cp.async.wait_group 0;" ::: "memory");
    __syncthreads();

    unsigned long long acc[4][4];
    #pragma unroll
    for (int i = 0; i < 4; ++i)
        #pragma unroll
        for (int j = 0; j < 4; ++j) acc[i][j] = 0ull;
    int cnt[4] = {0, 0, 0, 0};

    // ---------------- main loop ----------------
    for (int t = 0; t < NT; ++t) {
        const int buf = t & 1, nbuf = buf ^ 1;

        // bits for this thread's 4 consumption rows
        uint2 bw[4];
        #pragma unroll
        for (int i = 0; i < 4; ++i)
            bw[i] = *reinterpret_cast<const uint2*>(&sh_bits[buf][4 * tr + i][0]);
        if (rh == 0) {
            #pragma unroll
            for (int i = 0; i < 4; ++i)
                cnt[i] += __popc(bw[i].x) + __popc(bw[i].y);
        }

        const bool stg = (t + 1 < NT);
        if (stg) {
            cp16(&sh_e[nbuf][tid * 4], g_EW1 + (kbase + (t + 1) * KT) * NH + tid * 4);
            asm volatile("cp.async.commit_group;");
        }
        const int cnx = kbase + (t + 1) * KT + cl;
        const unsigned sae = (unsigned)__cvta_generic_to_shared(&sh_e[buf][0]) + rh * 32;

        #pragma unroll 4
        for (int b = 0; b < 16; ++b) {
            // 1) issue next-tile loads (independent of compute below)
            float2 v[4];
            if (stg) {
                #pragma unroll
                for (int j = 0; j < 4; ++j) {
                    int row = 64 * w + 4 * b + j;
                    v[j] = (cnx < VOCAB)
                         ? __ldcs(reinterpret_cast<const float2*>(sb + (long long)row * SRC_COLS + cnx))
                         : make_float2(0.f, 0.f);
                }
            }
            // 2) compute 4 k-columns: 8 N-cols x 4 rows each
            #pragma unroll
            for (int j = 0; j < 4; ++j) {
                const int k = 4 * b + j;
                const int bit = k >> 1;
                unsigned long long e0, e1, e2, e3;
                const unsigned sa = sae + k * 64;
                asm("ld.shared.v2.b64 {%0,%1}, [%2];"    : "=l"(e0), "=l"(e1) : "r"(sa));
                asm("ld.shared.v2.b64 {%0,%1}, [%2+16];" : "=l"(e2), "=l"(e3) : "r"(sa));
                #pragma unroll
                for (int i = 0; i < 4; ++i) {
                    const unsigned wr = (k & 1) ? bw[i].y : bw[i].x;
                    const float mf = ((wr >> bit) & 1u) ? 1.f : 0.f;
                    const unsigned long long m = pack2(mf, mf);
                    fma2(acc[i][0], e0, m);
                    fma2(acc[i][1], e1, m);
                    fma2(acc[i][2], e2, m);
                    fma2(acc[i][3], e3, m);
                }
            }
            // 3) consume loads: ballots + STS into next-tile bits
            if (stg) {
                #pragma unroll
                for (int j = 0; j < 4; ++j) {
                    unsigned q0 = __ballot_sync(0xffffffffu, v[j].x != 0.f);
                    unsigned q1 = __ballot_sync(0xffffffffu, v[j].y != 0.f);
                    if (lane == 0)
                        *reinterpret_cast<uint2*>(&sh_bits[nbuf][64 * w + 4 * b + j][0]) = make_uint2(q0, q1);
                }
            }
        }
        if (stg) asm volatile("cp.async.wait_group 0;" ::: "memory");
        __syncthreads();
    }

    // ---------------- write partials (column-major) ----------------
    #pragma unroll
    for (int i = 0; i < 4; ++i) {
        const int rg = row0 + 4 * tr + i;
        #pragma unroll
        for (int j = 0; j < 4; ++j) {
            float lo, hi;
            unpack2(acc[i][j], lo, hi);
            g_S[(part * 17 + 8 * rh + 2 * j + 0) * B_ROWS + rg] = lo;
            g_S[(part * 17 + 8 * rh + 2 * j + 1) * B_ROWS + rg] = hi;
        }
        if (rh == 0)
            g_S[(part * 17 + 16) * B_ROWS + rg] = (float)cnt[i];
    }
}

// ---------------------------------------------------------------------------
// Kernel 2: reduce K-split partials + MLP epilogue
// ---------------------------------------------------------------------------
__global__ void mlp_kernel(const float* __restrict__ src, const float* __restrict__ W1,
                           const float* __restrict__ b1, const float* __restrict__ W2,
                           const float* __restrict__ b2, float* __restrict__ out) {
    int r = blockIdx.x * blockDim.x + threadIdx.x;
    if (r >= B_ROWS) return;

    float s[17];
    #pragma unroll
    for (int n = 0; n < 17; ++n) s[n] = 0.f;
    #pragma unroll
    for (int p = 0; p < KSPLIT; ++p)
        #pragma unroll
        for (int n = 0; n < 17; ++n)
            s[n] += g_S[(p * 17 + n) * B_ROWS + r];

    const float inv = 1.f / s[16];
    const float d0 = src[(long long)r * SRC_COLS + 0];
    const float d1 = src[(long long)r * SRC_COLS + 1];

    float o0 = b2[0], o1 = b2[1];
    #pragma unroll
    for (int j = 0; j < NH; ++j) {
        float z = d0 * W1[j] + d1 * W1[NH + j] + s[j] * inv + b1[j];
        float h = tanhf(z);
        o0 += h * W2[2 * j + 0];
        o1 += h * W2[2 * j + 1];
    }
    out[2 * r + 0] = o0;
    out[2 * r + 1] = o1;
}

// ---------------------------------------------------------------------------
// Launch
// ---------------------------------------------------------------------------
extern "C" void kernel_launch(void* const* d_in, const int* in_sizes, int n_in,
                              void* d_out, int out_size) {
    int iSrc = 0, iEmb = 1, iW1 = 2, iB1 = 3, iW2 = 4, iB2 = 5;
    for (int i = 0; i < n_in; ++i) {
        int s = in_sizes[i];
        if      (s == B_ROWS * SRC_COLS)  iSrc = i;
        else if (s == VOCAB * EMB)        iEmb = i;
        else if (s == (NDEM + EMB) * NH)  iW1  = i;
        else if (s == NH)                 iB1  = i;
        else if (s == NH * 2)             iW2  = i;
        else if (s == 2)                  iB2  = i;
    }
    const float* src   = (const float*)d_in[iSrc];
    const float* embed = (const float*)d_in[iEmb];
    const float* W1    = (const float*)d_in[iW1];
    const float* b1    = (const float*)d_in[iB1];
    const float* W2    = (const float*)d_in[iW2];
    const float* b2    = (const float*)d_in[iB2];
    float* out = (float*)d_out;

    ew1_kernel<<<KPAD / 32, 512>>>(embed, W1);
    pool_kernel<<<NCTA, THREADS>>>(src);
    mlp_kernel<<<(B_ROWS + 255) / 256, 256>>>(src, W1, b1, W2, b2, out);
}

// round 13
// speedup vs baseline: 1.4314x; 1.1403x over previous
#include <cuda_runtime.h>
#include <cstdint>
#include <cmath>

// ---------------------------------------------------------------------------
// Problem constants
// ---------------------------------------------------------------------------
#define VOCAB     10000
#define NDEM      2
#define EMB       128
#define B_ROWS    16384
#define SRC_COLS  10002
#define NH        16
#define KPAD      10240
#define KSPLIT    16
#define KRANGE    (KPAD / KSPLIT)    // 640
#define KT        64                 // k-columns per pipeline tile
#define NT        (KRANGE / KT)      // 10
#define TM        256                // rows per CTA (1 row per thread)
#define THREADS   256
#define NCTA      ((B_ROWS / TM) * KSPLIT)   // 1024

// Scratch (__device__ globals: allocation-free rule)
__device__ float g_EW1[KPAD * NH];            // [vocab-col][16]
__device__ float g_S[KSPLIT * 17 * B_ROWS];   // 16 partials x (16 sums + count)

// ---------------------------------------------------------------------------
// packed f32x2 helpers
// ---------------------------------------------------------------------------
__device__ __forceinline__ void fma2(unsigned long long& d, unsigned long long a,
                                     unsigned long long b) {
    asm("fma.rn.f32x2 %0, %1, %2, %0;" : "+l"(d) : "l"(a), "l"(b));
}
__device__ __forceinline__ unsigned long long pack2(float lo, float hi) {
    unsigned long long r;
    asm("mov.b64 %0, {%1, %2};" : "=l"(r) : "r"(__float_as_uint(lo)), "r"(__float_as_uint(hi)));
    return r;
}
__device__ __forceinline__ void unpack2(unsigned long long v, float& lo, float& hi) {
    unsigned a, b;
    asm("mov.b64 {%0, %1}, %2;" : "=r"(a), "=r"(b) : "l"(v));
    lo = __uint_as_float(a); hi = __uint_as_float(b);
}
__device__ __forceinline__ void cp16(void* s, const void* g) {
    unsigned sa = (unsigned)__cvta_generic_to_shared(s);
    asm volatile("cp.async.cg.shared.global [%0], [%1], 16;" :: "r"(sa), "l"(g));
}

// ---------------------------------------------------------------------------
// Kernel 0: g_EW1[c][n] = sum_d embed[c][d] * W1[(2+d)*16+n]   (0 for c>=VOCAB)
// ---------------------------------------------------------------------------
__global__ __launch_bounds__(512) void ew1_kernel(const float* __restrict__ embed,
                                                  const float* __restrict__ W1) {
    __shared__ float sh_emb[32][EMB];
    __shared__ float sh_w1[EMB][NH];
    const int tid = threadIdx.x;
    const int c0  = blockIdx.x * 32;

    for (int i = tid; i < EMB * NH; i += 512)
        sh_w1[i >> 4][i & 15] = W1[NDEM * NH + i];
    for (int i = tid; i < 32 * EMB; i += 512) {
        int r = i >> 7, k = c0 + r;
        sh_emb[r][i & 127] = (k < VOCAB) ? embed[(long long)k * EMB + (i & 127)] : 0.f;
    }
    __syncthreads();

    const int r = tid >> 4, n = tid & 15, k = c0 + r;
    float a0 = 0.f, a1 = 0.f;
    #pragma unroll 16
    for (int d = 0; d < EMB; d += 2) {
        a0 += sh_emb[r][d]     * sh_w1[d][n];
        a1 += sh_emb[r][d + 1] * sh_w1[d + 1][n];
    }
    g_EW1[k * NH + n] = (k < VOCAB) ? (a0 + a1) : 0.f;
}

// ---------------------------------------------------------------------------
// Kernel 1: partial S = mask_tile @ EW1  (pipelined bitmask GEMM)
//   TM=256: warp w stages rows [32w, 32w+32); ONE float2 warp-load covers a
//   full row-tile (64 cols). Bit layout: col k -> word (k&1), bit (k>>1).
//   Consumption: thread tid owns row tid, all 16 N-cols:
//   per k: 4 broadcast LDS.v2.b64 + bit-extract + 8 fma2.  acc = 8 u64 = 16
//   regs -> ~50 live -> occ 4 (8 warps/SMSP) spill-free.
// ---------------------------------------------------------------------------
__global__ __launch_bounds__(THREADS, 4) void pool_kernel(const float* __restrict__ src) {
    __shared__ __align__(16) float sh_e[2][KT * NH];   // 2 x 4 KB
    __shared__ __align__(8)  uint2 sh_bits[2][TM];     // 2 x 2 KB

    const int tid  = threadIdx.x;
    const int w    = tid >> 5;
    const int lane = tid & 31;
    const int mtile = blockIdx.x >> 4;
    const int part  = blockIdx.x & (KSPLIT - 1);
    const int row0  = mtile * TM;
    const int kbase = part * KRANGE;
    const float* sb = src + (long long)row0 * SRC_COLS + NDEM;
    const int cl = 2 * lane;                 // lane's (even) col offset in a tile

    // ---------------- prologue: stage tile 0 ----------------
    cp16(&sh_e[0][tid * 4], g_EW1 + kbase * NH + tid * 4);
    asm volatile("cp.async.commit_group;");
    {
        const int c = kbase + cl;
        #pragma unroll 2
        for (int b = 0; b < 8; ++b) {
            float2 v[4];
            #pragma unroll
            for (int j = 0; j < 4; ++j) {
                int row = 32 * w + 4 * b + j;
                v[j] = (c < VOCAB)
                     ? __ldcs(reinterpret_cast<const float2*>(sb + (long long)row * SRC_COLS + c))
                     : make_float2(0.f, 0.f);
            }
            #pragma unroll
            for (int j = 0; j < 4; ++j) {
                unsigned w0 = __ballot_sync(0xffffffffu, v[j].x != 0.f);
                unsigned w1 = __ballot_sync(0xffffffffu, v[j].y != 0.f);
                if (lane == 0) sh_bits[0][32 * w + 4 * b + j] = make_uint2(w0, w1);
            }
        }
    }
    asm volatile("cp.async.wait_group 0;" ::: "memory");
    __syncthreads();

    unsigned long long acc[8];
    #pragma unroll
    for (int i = 0; i < 8; ++i) acc[i] = 0ull;
    int cnt = 0;

    // ---------------- main loop ----------------
    for (int t = 0; t < NT; ++t) {
        const int buf = t & 1, nbuf = buf ^ 1;

        const uint2 bw = sh_bits[buf][tid];          // this thread's row bits
        cnt += __popc(bw.x) + __popc(bw.y);

        const bool stg = (t + 1 < NT);
        if (stg) {
            cp16(&sh_e[nbuf][tid * 4], g_EW1 + (kbase + (t + 1) * KT) * NH + tid * 4);
            asm volatile("cp.async.commit_group;");
        }
        const int cnx = kbase + (t + 1) * KT + cl;
        const unsigned sae = (unsigned)__cvta_generic_to_shared(&sh_e[buf][0]);

        #pragma unroll 2
        for (int b = 0; b < 8; ++b) {
            // 1) issue next-tile loads (consumed by ballots at step 3)
            float2 v[4];
            if (stg) {
                #pragma unroll
                for (int j = 0; j < 4; ++j) {
                    int row = 32 * w + 4 * b + j;
                    v[j] = (cnx < VOCAB)
                         ? __ldcs(reinterpret_cast<const float2*>(sb + (long long)row * SRC_COLS + cnx))
                         : make_float2(0.f, 0.f);
                }
            }
            // 2) compute 8 k-columns of current tile for this thread's row
            #pragma unroll
            for (int kk = 0; kk < 8; ++kk) {
                const int k = 8 * b + kk;
                const int bit = k >> 1;
                const unsigned wr = (k & 1) ? bw.y : bw.x;
                const float mf = ((wr >> bit) & 1u) ? 1.f : 0.f;
                const unsigned long long m = pack2(mf, mf);
                unsigned long long e0, e1, e2, e3;
                const unsigned sa = sae + k * 64;
                asm("ld.shared.v2.b64 {%0,%1}, [%2];"    : "=l"(e0), "=l"(e1) : "r"(sa));
                asm("ld.shared.v2.b64 {%0,%1}, [%2+16];" : "=l"(e2), "=l"(e3) : "r"(sa));
                fma2(acc[0], e0, m); fma2(acc[1], e1, m);
                fma2(acc[2], e2, m); fma2(acc[3], e3, m);
                asm("ld.shared.v2.b64 {%0,%1}, [%2+32];" : "=l"(e0), "=l"(e1) : "r"(sa));
                asm("ld.shared.v2.b64 {%0,%1}, [%2+48];" : "=l"(e2), "=l"(e3) : "r"(sa));
                fma2(acc[4], e0, m); fma2(acc[5], e1, m);
                fma2(acc[6], e2, m); fma2(acc[7], e3, m);
            }
            // 3) ballots + STS into next-tile bits
            if (stg) {
                #pragma unroll
                for (int j = 0; j < 4; ++j) {
                    unsigned q0 = __ballot_sync(0xffffffffu, v[j].x != 0.f);
                    unsigned q1 = __ballot_sync(0xffffffffu, v[j].y != 0.f);
                    if (lane == 0) sh_bits[nbuf][32 * w + 4 * b + j] = make_uint2(q0, q1);
                }
            }
        }
        if (stg) asm volatile("cp.async.wait_group 0;" ::: "memory");
        __syncthreads();
    }

    // ---------------- write partials (column-major, coalesced) ----------------
    const int rg = row0 + tid;
    #pragma unroll
    for (int i = 0; i < 8; ++i) {
        float lo, hi;
        unpack2(acc[i], lo, hi);
        g_S[(part * 17 + 2 * i + 0) * B_ROWS + rg] = lo;
        g_S[(part * 17 + 2 * i + 1) * B_ROWS + rg] = hi;
    }
    g_S[(part * 17 + 16) * B_ROWS + rg] = (float)cnt;
}

// ---------------------------------------------------------------------------
// Kernel 2: reduce K-split partials + MLP epilogue
// ---------------------------------------------------------------------------
__global__ void mlp_kernel(const float* __restrict__ src, const float* __restrict__ W1,
                           const float* __restrict__ b1, const float* __restrict__ W2,
                           const float* __restrict__ b2, float* __restrict__ out) {
    int r = blockIdx.x * blockDim.x + threadIdx.x;
    if (r >= B_ROWS) return;

    float s[17];
    #pragma unroll
    for (int n = 0; n < 17; ++n) s[n] = 0.f;
    #pragma unroll
    for (int p = 0; p < KSPLIT; ++p)
        #pragma unroll
        for (int n = 0; n < 17; ++n)
            s[n] += g_S[(p * 17 + n) * B_ROWS + r];

    const float inv = 1.f / s[16];
    const float d0 = src[(long long)r * SRC_COLS + 0];
    const float d1 = src[(long long)r * SRC_COLS + 1];

    float o0 = b2[0], o1 = b2[1];
    #pragma unroll
    for (int j = 0; j < NH; ++j) {
        float z = d0 * W1[j] + d1 * W1[NH + j] + s[j] * inv + b1[j];
        float h = tanhf(z);
        o0 += h * W2[2 * j + 0];
        o1 += h * W2[2 * j + 1];
    }
    out[2 * r + 0] = o0;
    out[2 * r + 1] = o1;
}

// ---------------------------------------------------------------------------
// Launch
// ---------------------------------------------------------------------------
extern "C" void kernel_launch(void* const* d_in, const int* in_sizes, int n_in,
                              void* d_out, int out_size) {
    int iSrc = 0, iEmb = 1, iW1 = 2, iB1 = 3, iW2 = 4, iB2 = 5;
    for (int i = 0; i < n_in; ++i) {
        int s = in_sizes[i];
        if      (s == B_ROWS * SRC_COLS)  iSrc = i;
        else if (s == VOCAB * EMB)        iEmb = i;
        else if (s == (NDEM + EMB) * NH)  iW1  = i;
        else if (s == NH)                 iB1  = i;
        else if (s == NH * 2)             iW2  = i;
        else if (s == 2)                  iB2  = i;
    }
    const float* src   = (const float*)d_in[iSrc];
    const float* embed = (const float*)d_in[iEmb];
    const float* W1    = (const float*)d_in[iW1];
    const float* b1    = (const float*)d_in[iB1];
    const float* W2    = (const float*)d_in[iW2];
    const float* b2    = (const float*)d_in[iB2];
    float* out = (float*)d_out;

    ew1_kernel<<<KPAD / 32, 512>>>(embed, W1);
    pool_kernel<<<NCTA, THREADS>>>(src);
    mlp_kernel<<<(B_ROWS + 255) / 256, 256>>>(src, W1, b1, W2, b2, out);
}

// round 14
// speedup vs baseline: 1.6215x; 1.1328x over previous
#include <cuda_runtime.h>
#include <cstdint>
#include <cmath>

// ---------------------------------------------------------------------------
// Problem constants
// ---------------------------------------------------------------------------
#define VOCAB     10000
#define NDEM      2
#define EMB       128
#define B_ROWS    16384
#define SRC_COLS  10002
#define NH        16
#define KPAD      10240
#define KSPLIT    16
#define KRANGE    (KPAD / KSPLIT)    // 640
#define KT        64                 // k-columns per pipeline tile
#define NT        (KRANGE / KT)      // 10
#define NG        16                 // 4-col groups per tile
#define TM        256                // rows per CTA (1 row per thread)
#define THREADS   256
#define NCTA      ((B_ROWS / TM) * KSPLIT)   // 1024
#define EST       80                 // table entry stride bytes (64B data + pad)

// Scratch (__device__ globals: allocation-free rule)
__device__ float g_EW1[KPAD * NH];            // [vocab-col][16]
__device__ float g_S[KSPLIT * 17 * B_ROWS];   // 16 partials x (16 sums + count)

// ---------------------------------------------------------------------------
// helpers
// ---------------------------------------------------------------------------
__device__ __forceinline__ void fma2(unsigned long long& d, unsigned long long a,
                                     unsigned long long b) {
    asm("fma.rn.f32x2 %0, %1, %2, %0;" : "+l"(d) : "l"(a), "l"(b));
}
__device__ __forceinline__ unsigned long long pack2(float lo, float hi) {
    unsigned long long r;
    asm("mov.b64 %0, {%1, %2};" : "=l"(r) : "r"(__float_as_uint(lo)), "r"(__float_as_uint(hi)));
    return r;
}
__device__ __forceinline__ void cp16(void* s, const void* g) {
    unsigned sa = (unsigned)__cvta_generic_to_shared(s);
    asm volatile("cp.async.cg.shared.global [%0], [%1], 16;" :: "r"(sa), "l"(g));
}

// ---------------------------------------------------------------------------
// Kernel 0: g_EW1[c][n] = sum_d embed[c][d] * W1[(2+d)*16+n]   (0 for c>=VOCAB)
// ---------------------------------------------------------------------------
__global__ __launch_bounds__(512) void ew1_kernel(const float* __restrict__ embed,
                                                  const float* __restrict__ W1) {
    __shared__ float sh_emb[32][EMB];
    __shared__ float sh_w1[EMB][NH];
    const int tid = threadIdx.x;
    const int c0  = blockIdx.x * 32;

    for (int i = tid; i < EMB * NH; i += 512)
        sh_w1[i >> 4][i & 15] = W1[NDEM * NH + i];
    for (int i = tid; i < 32 * EMB; i += 512) {
        int r = i >> 7, k = c0 + r;
        sh_emb[r][i & 127] = (k < VOCAB) ? embed[(long long)k * EMB + (i & 127)] : 0.f;
    }
    __syncthreads();

    const int r = tid >> 4, n = tid & 15, k = c0 + r;
    float a0 = 0.f, a1 = 0.f;
    #pragma unroll 16
    for (int d = 0; d < EMB; d += 2) {
        a0 += sh_emb[r][d]     * sh_w1[d][n];
        a1 += sh_emb[r][d + 1] * sh_w1[d + 1][n];
    }
    g_EW1[k * NH + n] = (k < VOCAB) ? (a0 + a1) : 0.f;
}

// ---------------------------------------------------------------------------
// Kernel 1: partial S = mask_tile @ EW1 via 4-bit subset-sum table.
//   R13 skeleton: TM=256, 1 row/thread, occ 4. Bit layout: col k -> word
//   (k&1), bit (k>>1).  Group g covers cols 4g..4g+3; nibble mapping and
//   table build are the R9-proven ones:
//     nibble m = ((bw.x>>2g)&3) | (((bw.y>>2g)&3)<<2)
//     bit0->e[4g], bit1->e[4g+2], bit2->e[4g+1], bit3->e[4g+3]
//   Per group: 3 ALU + 4 LDS.v4 + 16 FADD  (vs 16 FFMA+LDS per SINGLE k before)
// ---------------------------------------------------------------------------
__global__ __launch_bounds__(THREADS, 4) void pool_kernel(const float* __restrict__ src) {
    __shared__ __align__(16) float sh_tbl[NG * 16 * (EST / 4)];  // 20 KB
    __shared__ __align__(16) float sh_e[2][KT * NH];             // 8 KB
    __shared__ __align__(8)  uint2 sh_bits[2][TM];               // 4 KB

    const int tid  = threadIdx.x;
    const int w    = tid >> 5;
    const int lane = tid & 31;
    const int mtile = blockIdx.x >> 4;
    const int part  = blockIdx.x & (KSPLIT - 1);
    const int row0  = mtile * TM;
    const int kbase = part * KRANGE;
    const float* sb = src + (long long)row0 * SRC_COLS + NDEM;
    const int cl = 2 * lane;                 // lane's (even) col offset in a tile
    const unsigned tbl = (unsigned)__cvta_generic_to_shared(&sh_tbl[0]);

    // this thread's table item: group bg, mask bm
    const int bg = tid >> 4, bm = tid & 15;
    const unsigned long long q0 = pack2((bm & 1) ? 1.f : 0.f, (bm & 1) ? 1.f : 0.f);  // e[4g]
    const unsigned long long q1 = pack2((bm & 2) ? 1.f : 0.f, (bm & 2) ? 1.f : 0.f);  // e[4g+2]
    const unsigned long long q2 = pack2((bm & 4) ? 1.f : 0.f, (bm & 4) ? 1.f : 0.f);  // e[4g+1]
    const unsigned long long q3 = pack2((bm & 8) ? 1.f : 0.f, (bm & 8) ? 1.f : 0.f);  // e[4g+3]
    const unsigned tdst = tbl + (bg * 16 + bm) * EST;

    // ---------------- prologue: stage tile 0 ----------------
    cp16(&sh_e[0][tid * 4], g_EW1 + kbase * NH + tid * 4);
    asm volatile("cp.async.commit_group;");
    {
        const int c = kbase + cl;
        #pragma unroll
        for (int bb = 0; bb < 4; ++bb) {
            float2 v[8];
            #pragma unroll
            for (int j = 0; j < 8; ++j) {
                int row = 32 * w + 8 * bb + j;
                v[j] = (c < VOCAB)
                     ? __ldcs(reinterpret_cast<const float2*>(sb + (long long)row * SRC_COLS + c))
                     : make_float2(0.f, 0.f);
            }
            #pragma unroll
            for (int j = 0; j < 8; ++j) {
                unsigned b0 = __ballot_sync(0xffffffffu, v[j].x != 0.f);
                unsigned b1 = __ballot_sync(0xffffffffu, v[j].y != 0.f);
                if (lane == 0) sh_bits[0][32 * w + 8 * bb + j] = make_uint2(b0, b1);
            }
        }
    }
    asm volatile("cp.async.wait_group 0;" ::: "memory");
    __syncthreads();

    float acc[16];
    #pragma unroll
    for (int i = 0; i < 16; ++i) acc[i] = 0.f;
    int cnt = 0;

    // ---------------- main loop ----------------
    for (int t = 0; t < NT; ++t) {
        const int buf = t & 1, nbuf = buf ^ 1;

        // ---- build subset-sum table from sh_e[buf] (R9-proven mapping) ----
        {
            const unsigned eb = (unsigned)__cvta_generic_to_shared(&sh_e[buf][0]) + bg * 256;
            #pragma unroll
            for (int i = 0; i < 8; ++i) {
                unsigned long long e0, e1, e2, e3, s = 0ull;
                asm("ld.shared.b64 %0, [%1];"     : "=l"(e0) : "r"(eb + i * 8));
                asm("ld.shared.b64 %0, [%1+64];"  : "=l"(e1) : "r"(eb + i * 8));
                asm("ld.shared.b64 %0, [%1+128];" : "=l"(e2) : "r"(eb + i * 8));
                asm("ld.shared.b64 %0, [%1+192];" : "=l"(e3) : "r"(eb + i * 8));
                fma2(s, e0, q0);   // col 4g
                fma2(s, e2, q1);   // col 4g+2
                fma2(s, e1, q2);   // col 4g+1
                fma2(s, e3, q3);   // col 4g+3
                asm volatile("st.shared.b64 [%0], %1;" :: "r"(tdst + i * 8), "l"(s));
            }
        }
        __syncthreads();   // table ready

        const uint2 bw = sh_bits[buf][tid];
        cnt += __popc(bw.x) + __popc(bw.y);

        const bool stg = (t + 1 < NT);
        if (stg) {
            cp16(&sh_e[nbuf][tid * 4], g_EW1 + (kbase + (t + 1) * KT) * NH + tid * 4);
            asm volatile("cp.async.commit_group;");
        }
        const int cnx = kbase + (t + 1) * KT + cl;

        #pragma unroll
        for (int bb = 0; bb < 4; ++bb) {
            // 1) issue next-tile loads (8 rows; consumed by ballots below)
            float2 v[8];
            if (stg) {
                #pragma unroll
                for (int j = 0; j < 8; ++j) {
                    int row = 32 * w + 8 * bb + j;
                    v[j] = (cnx < VOCAB)
                         ? __ldcs(reinterpret_cast<const float2*>(sb + (long long)row * SRC_COLS + cnx))
                         : make_float2(0.f, 0.f);
                }
            }
            // 2) consume 4 groups (16 k-columns) via table lookups
            #pragma unroll
            for (int gg = 0; gg < 4; ++gg) {
                const int g = 4 * bb + gg;
                const unsigned m = ((bw.x >> (2 * g)) & 3u) | (((bw.y >> (2 * g)) & 3u) << 2);
                const unsigned a = tbl + (g * 16 + m) * EST;
                float4 t0, t1, t2, t3;
                asm("ld.shared.v4.f32 {%0,%1,%2,%3}, [%4];"
                    : "=f"(t0.x), "=f"(t0.y), "=f"(t0.z), "=f"(t0.w) : "r"(a));
                asm("ld.shared.v4.f32 {%0,%1,%2,%3}, [%4+16];"
                    : "=f"(t1.x), "=f"(t1.y), "=f"(t1.z), "=f"(t1.w) : "r"(a));
                asm("ld.shared.v4.f32 {%0,%1,%2,%3}, [%4+32];"
                    : "=f"(t2.x), "=f"(t2.y), "=f"(t2.z), "=f"(t2.w) : "r"(a));
                asm("ld.shared.v4.f32 {%0,%1,%2,%3}, [%4+48];"
                    : "=f"(t3.x), "=f"(t3.y), "=f"(t3.z), "=f"(t3.w) : "r"(a));
                acc[0]  += t0.x; acc[1]  += t0.y; acc[2]  += t0.z; acc[3]  += t0.w;
                acc[4]  += t1.x; acc[5]  += t1.y; acc[6]  += t1.z; acc[7]  += t1.w;
                acc[8]  += t2.x; acc[9]  += t2.y; acc[10] += t2.z; acc[11] += t2.w;
                acc[12] += t3.x; acc[13] += t3.y; acc[14] += t3.z; acc[15] += t3.w;
            }
            // 3) ballots + STS into next-tile bits
            if (stg) {
                #pragma unroll
                for (int j = 0; j < 8; ++j) {
                    unsigned p0 = __ballot_sync(0xffffffffu, v[j].x != 0.f);
                    unsigned p1 = __ballot_sync(0xffffffffu, v[j].y != 0.f);
                    if (lane == 0) sh_bits[nbuf][32 * w + 8 * bb + j] = make_uint2(p0, p1);
                }
            }
        }
        if (stg) asm volatile("cp.async.wait_group 0;" ::: "memory");
        __syncthreads();   // bits[nbuf] + e[nbuf] ready; table free to rebuild
    }

    // ---------------- write partials (column-major, coalesced) ----------------
    const int rg = row0 + tid;
    #pragma unroll
    for (int n = 0; n < 16; ++n)
        g_S[(part * 17 + n) * B_ROWS + rg] = acc[n];
    g_S[(part * 17 + 16) * B_ROWS + rg] = (float)cnt;
}

// ---------------------------------------------------------------------------
// Kernel 2: reduce K-split partials + MLP epilogue
// ---------------------------------------------------------------------------
__global__ void mlp_kernel(const float* __restrict__ src, const float* __restrict__ W1,
                           const float* __restrict__ b1, const float* __restrict__ W2,
                           const float* __restrict__ b2, float* __restrict__ out) {
    int r = blockIdx.x * blockDim.x + threadIdx.x;
    if (r >= B_ROWS) return;

    float s[17];
    #pragma unroll
    for (int n = 0; n < 17; ++n) s[n] = 0.f;
    #pragma unroll
    for (int p = 0; p < KSPLIT; ++p)
        #pragma unroll
        for (int n = 0; n < 17; ++n)
            s[n] += g_S[(p * 17 + n) * B_ROWS + r];

    const float inv = 1.f / s[16];
    const float d0 = src[(long long)r * SRC_COLS + 0];
    const float d1 = src[(long long)r * SRC_COLS + 1];

    float o0 = b2[0], o1 = b2[1];
    #pragma unroll
    for (int j = 0; j < NH; ++j) {
        float z = d0 * W1[j] + d1 * W1[NH + j] + s[j] * inv + b1[j];
        float h = tanhf(z);
        o0 += h * W2[2 * j + 0];
        o1 += h * W2[2 * j + 1];
    }
    out[2 * r + 0] = o0;
    out[2 * r + 1] = o1;
}

// ---------------------------------------------------------------------------
// Launch
// ---------------------------------------------------------------------------
extern "C" void kernel_launch(void* const* d_in, const int* in_sizes, int n_in,
                              void* d_out, int out_size) {
    int iSrc = 0, iEmb = 1, iW1 = 2, iB1 = 3, iW2 = 4, iB2 = 5;
    for (int i = 0; i < n_in; ++i) {
        int s = in_sizes[i];
        if      (s == B_ROWS * SRC_COLS)  iSrc = i;
        else if (s == VOCAB * EMB)        iEmb = i;
        else if (s == (NDEM + EMB) * NH)  iW1  = i;
        else if (s == NH)                 iB1  = i;
        else if (s == NH * 2)             iW2  = i;
        else if (s == 2)                  iB2  = i;
    }
    const float* src   = (const float*)d_in[iSrc];
    const float* embed = (const float*)d_in[iEmb];
    const float* W1    = (const float*)d_in[iW1];
    const float* b1    = (const float*)d_in[iB1];
    const float* W2    = (const float*)d_in[iW2];
    const float* b2    = (const float*)d_in[iB2];
    float* out = (float*)d_out;

    ew1_kernel<<<KPAD / 32, 512>>>(embed, W1);
    pool_kernel<<<NCTA, THREADS>>>(src);
    mlp_kernel<<<(B_ROWS + 255) / 256, 256>>>(src, W1, b1, W2, b2, out);
}

// round 15
// speedup vs baseline: 1.9675x; 1.2134x over previous
#include <cuda_runtime.h>
#include <cstdint>
#include <cmath>

// ---------------------------------------------------------------------------
// Problem constants
// ---------------------------------------------------------------------------
#define VOCAB     10000
#define NDEM      2
#define EMB       128
#define B_ROWS    16384
#define SRC_COLS  10002
#define NH        16
#define KPAD      10240
#define KSPLIT    8
#define KRANGE    (KPAD / KSPLIT)    // 1280
#define KT        64                 // k-columns per pipeline tile
#define NT        (KRANGE / KT)      // 20
#define NG        16                 // 4-col groups per tile
#define TM        256                // rows per CTA (1 row per thread)
#define THREADS   256
#define NCTA      ((B_ROWS / TM) * KSPLIT)   // 512 -> single wave at occ 4
#define EST       88                 // table entry stride: 22 words -> all 16
                                     // entries on distinct banks (22m mod 32
                                     // distinct for m=0..15); 8B-aligned

// Scratch (__device__ globals: allocation-free rule)
__device__ float g_EW1[KPAD * NH];            // [vocab-col][16]
__device__ float g_S[KSPLIT * 17 * B_ROWS];   // 8 partials x (16 sums + count)

// ---------------------------------------------------------------------------
// helpers
// ---------------------------------------------------------------------------
__device__ __forceinline__ void fma2(unsigned long long& d, unsigned long long a,
                                     unsigned long long b) {
    asm("fma.rn.f32x2 %0, %1, %2, %0;" : "+l"(d) : "l"(a), "l"(b));
}
__device__ __forceinline__ unsigned long long pack2(float lo, float hi) {
    unsigned long long r;
    asm("mov.b64 %0, {%1, %2};" : "=l"(r) : "r"(__float_as_uint(lo)), "r"(__float_as_uint(hi)));
    return r;
}
__device__ __forceinline__ void cp16(void* s, const void* g) {
    unsigned sa = (unsigned)__cvta_generic_to_shared(s);
    asm volatile("cp.async.cg.shared.global [%0], [%1], 16;" :: "r"(sa), "l"(g));
}

// ---------------------------------------------------------------------------
// Kernel 0: g_EW1[c][n] = sum_d embed[c][d] * W1[(2+d)*16+n]   (0 for c>=VOCAB)
// ---------------------------------------------------------------------------
__global__ __launch_bounds__(512) void ew1_kernel(const float* __restrict__ embed,
                                                  const float* __restrict__ W1) {
    __shared__ float sh_emb[32][EMB];
    __shared__ float sh_w1[EMB][NH];
    const int tid = threadIdx.x;
    const int c0  = blockIdx.x * 32;

    for (int i = tid; i < EMB * NH; i += 512)
        sh_w1[i >> 4][i & 15] = W1[NDEM * NH + i];
    for (int i = tid; i < 32 * EMB; i += 512) {
        int r = i >> 7, k = c0 + r;
        sh_emb[r][i & 127] = (k < VOCAB) ? embed[(long long)k * EMB + (i & 127)] : 0.f;
    }
    __syncthreads();

    const int r = tid >> 4, n = tid & 15, k = c0 + r;
    float a0 = 0.f, a1 = 0.f;
    #pragma unroll 16
    for (int d = 0; d < EMB; d += 2) {
        a0 += sh_emb[r][d]     * sh_w1[d][n];
        a1 += sh_emb[r][d + 1] * sh_w1[d + 1][n];
    }
    g_EW1[k * NH + n] = (k < VOCAB) ? (a0 + a1) : 0.f;
}

// ---------------------------------------------------------------------------
// Kernel 1: partial S = mask_tile @ EW1 via 4-bit subset-sum table.
//   R14 chassis (TM=256, 1 row/thread, occ 4), two changes:
//   (a) EST=88 + 8B v2.f32 table reads -> conflict-free lookups
//   (b) KSPLIT=8 -> 512 CTAs, single wave
//   Bit layout: col k -> word (k&1), bit (k>>1). Nibble mapping (R9-proven):
//     m = ((bw.x>>2g)&3) | (((bw.y>>2g)&3)<<2)
//     bit0->e[4g], bit1->e[4g+2], bit2->e[4g+1], bit3->e[4g+3]
// ---------------------------------------------------------------------------
__global__ __launch_bounds__(THREADS, 4) void pool_kernel(const float* __restrict__ src) {
    __shared__ __align__(16) float sh_tbl[NG * 16 * (EST / 4)];  // 22.5 KB
    __shared__ __align__(16) float sh_e[2][KT * NH];             // 8 KB
    __shared__ __align__(8)  uint2 sh_bits[2][TM];               // 4 KB

    const int tid  = threadIdx.x;
    const int w    = tid >> 5;
    const int lane = tid & 31;
    const int mtile = blockIdx.x >> 3;           // / KSPLIT
    const int part  = blockIdx.x & (KSPLIT - 1);
    const int row0  = mtile * TM;
    const int kbase = part * KRANGE;
    const float* sb = src + (long long)row0 * SRC_COLS + NDEM;
    const int cl = 2 * lane;                 // lane's (even) col offset in a tile
    const unsigned tbl = (unsigned)__cvta_generic_to_shared(&sh_tbl[0]);

    // this thread's table item: group bg, mask bm
    const int bg = tid >> 4, bm = tid & 15;
    const unsigned long long q0 = pack2((bm & 1) ? 1.f : 0.f, (bm & 1) ? 1.f : 0.f);  // e[4g]
    const unsigned long long q1 = pack2((bm & 2) ? 1.f : 0.f, (bm & 2) ? 1.f : 0.f);  // e[4g+2]
    const unsigned long long q2 = pack2((bm & 4) ? 1.f : 0.f, (bm & 4) ? 1.f : 0.f);  // e[4g+1]
    const unsigned long long q3 = pack2((bm & 8) ? 1.f : 0.f, (bm & 8) ? 1.f : 0.f);  // e[4g+3]
    const unsigned tdst = tbl + (bg * 16 + bm) * EST;

    // ---------------- prologue: stage tile 0 ----------------
    cp16(&sh_e[0][tid * 4], g_EW1 + kbase * NH + tid * 4);
    asm volatile("cp.async.commit_group;");
    {
        const int c = kbase + cl;
        #pragma unroll
        for (int bb = 0; bb < 4; ++bb) {
            float2 v[8];
            #pragma unroll
            for (int j = 0; j < 8; ++j) {
                int row = 32 * w + 8 * bb + j;
                v[j] = (c < VOCAB)
                     ? __ldcs(reinterpret_cast<const float2*>(sb + (long long)row * SRC_COLS + c))
                     : make_float2(0.f, 0.f);
            }
            #pragma unroll
            for (int j = 0; j < 8; ++j) {
                unsigned b0 = __ballot_sync(0xffffffffu, v[j].x != 0.f);
                unsigned b1 = __ballot_sync(0xffffffffu, v[j].y != 0.f);
                if (lane == 0) sh_bits[0][32 * w + 8 * bb + j] = make_uint2(b0, b1);
            }
        }
    }
    asm volatile("cp.async.wait_group 0;" ::: "memory");
    __syncthreads();

    float acc[16];
    #pragma unroll
    for (int i = 0; i < 16; ++i) acc[i] = 0.f;
    int cnt = 0;

    // ---------------- main loop ----------------
    for (int t = 0; t < NT; ++t) {
        const int buf = t & 1, nbuf = buf ^ 1;

        // ---- build subset-sum table from sh_e[buf] ----
        {
            const unsigned eb = (unsigned)__cvta_generic_to_shared(&sh_e[buf][0]) + bg * 256;
            #pragma unroll
            for (int i = 0; i < 8; ++i) {
                unsigned long long e0, e1, e2, e3, s = 0ull;
                asm("ld.shared.b64 %0, [%1];"     : "=l"(e0) : "r"(eb + i * 8));
                asm("ld.shared.b64 %0, [%1+64];"  : "=l"(e1) : "r"(eb + i * 8));
                asm("ld.shared.b64 %0, [%1+128];" : "=l"(e2) : "r"(eb + i * 8));
                asm("ld.shared.b64 %0, [%1+192];" : "=l"(e3) : "r"(eb + i * 8));
                fma2(s, e0, q0);   // col 4g
                fma2(s, e2, q1);   // col 4g+2
                fma2(s, e1, q2);   // col 4g+1
                fma2(s, e3, q3);   // col 4g+3
                asm volatile("st.shared.b64 [%0], %1;" :: "r"(tdst + i * 8), "l"(s));
            }
        }
        __syncthreads();   // table ready

        const uint2 bw = sh_bits[buf][tid];
        cnt += __popc(bw.x) + __popc(bw.y);

        const bool stg = (t + 1 < NT);
        if (stg) {
            cp16(&sh_e[nbuf][tid * 4], g_EW1 + (kbase + (t + 1) * KT) * NH + tid * 4);
            asm volatile("cp.async.commit_group;");
        }
        const int cnx = kbase + (t + 1) * KT + cl;

        #pragma unroll
        for (int bb = 0; bb < 4; ++bb) {
            // 1) issue next-tile loads (8 rows; consumed by ballots below)
            float2 v[8];
            if (stg) {
                #pragma unroll
                for (int j = 0; j < 8; ++j) {
                    int row = 32 * w + 8 * bb + j;
                    v[j] = (cnx < VOCAB)
                         ? __ldcs(reinterpret_cast<const float2*>(sb + (long long)row * SRC_COLS + cnx))
                         : make_float2(0.f, 0.f);
                }
            }
            // 2) consume 4 groups (16 k-columns); conflict-free 8B lookups
            #pragma unroll
            for (int gg = 0; gg < 4; ++gg) {
                const int g = 4 * bb + gg;
                const unsigned m = ((bw.x >> (2 * g)) & 3u) | (((bw.y >> (2 * g)) & 3u) << 2);
                const unsigned a = tbl + (g * 16 + m) * EST;
                float x0, x1, x2, x3;
                asm("ld.shared.v2.f32 {%0,%1}, [%2];"    : "=f"(x0), "=f"(x1) : "r"(a));
                asm("ld.shared.v2.f32 {%0,%1}, [%2+8];"  : "=f"(x2), "=f"(x3) : "r"(a));
                acc[0] += x0; acc[1] += x1; acc[2] += x2; acc[3] += x3;
                asm("ld.shared.v2.f32 {%0,%1}, [%2+16];" : "=f"(x0), "=f"(x1) : "r"(a));
                asm("ld.shared.v2.f32 {%0,%1}, [%2+24];" : "=f"(x2), "=f"(x3) : "r"(a));
                acc[4] += x0; acc[5] += x1; acc[6] += x2; acc[7] += x3;
                asm("ld.shared.v2.f32 {%0,%1}, [%2+32];" : "=f"(x0), "=f"(x1) : "r"(a));
                asm("ld.shared.v2.f32 {%0,%1}, [%2+40];" : "=f"(x2), "=f"(x3) : "r"(a));
                acc[8]  += x0; acc[9]  += x1; acc[10] += x2; acc[11] += x3;
                asm("ld.shared.v2.f32 {%0,%1}, [%2+48];" : "=f"(x0), "=f"(x1) : "r"(a));
                asm("ld.shared.v2.f32 {%0,%1}, [%2+56];" : "=f"(x2), "=f"(x3) : "r"(a));
                acc[12] += x0; acc[13] += x1; acc[14] += x2; acc[15] += x3;
            }
            // 3) ballots + STS into next-tile bits
            if (stg) {
                #pragma unroll
                for (int j = 0; j < 8; ++j) {
                    unsigned p0 = __ballot_sync(0xffffffffu, v[j].x != 0.f);
                    unsigned p1 = __ballot_sync(0xffffffffu, v[j].y != 0.f);
                    if (lane == 0) sh_bits[nbuf][32 * w + 8 * bb + j] = make_uint2(p0, p1);
                }
            }
        }
        if (stg) asm volatile("cp.async.wait_group 0;" ::: "memory");
        __syncthreads();   // bits[nbuf] + e[nbuf] ready; table free to rebuild
    }

    // ---------------- write partials (column-major, coalesced) ----------------
    const int rg = row0 + tid;
    #pragma unroll
    for (int n = 0; n < 16; ++n)
        g_S[(part * 17 + n) * B_ROWS + rg] = acc[n];
    g_S[(part * 17 + 16) * B_ROWS + rg] = (float)cnt;
}

// ---------------------------------------------------------------------------
// Kernel 2: reduce K-split partials + MLP epilogue
// ---------------------------------------------------------------------------
__global__ void mlp_kernel(const float* __restrict__ src, const float* __restrict__ W1,
                           const float* __restrict__ b1, const float* __restrict__ W2,
                           const float* __restrict__ b2, float* __restrict__ out) {
    int r = blockIdx.x * blockDim.x + threadIdx.x;
    if (r >= B_ROWS) return;

    float s[17];
    #pragma unroll
    for (int n = 0; n < 17; ++n) s[n] = 0.f;
    #pragma unroll
    for (int p = 0; p < KSPLIT; ++p)
        #pragma unroll
        for (int n = 0; n < 17; ++n)
            s[n] += g_S[(p * 17 + n) * B_ROWS + r];

    const float inv = 1.f / s[16];
    const float d0 = src[(long long)r * SRC_COLS + 0];
    const float d1 = src[(long long)r * SRC_COLS + 1];

    float o0 = b2[0], o1 = b2[1];
    #pragma unroll
    for (int j = 0; j < NH; ++j) {
        float z = d0 * W1[j] + d1 * W1[NH + j] + s[j] * inv + b1[j];
        float h = tanhf(z);
        o0 += h * W2[2 * j + 0];
        o1 += h * W2[2 * j + 1];
    }
    out[2 * r + 0] = o0;
    out[2 * r + 1] = o1;
}

// ---------------------------------------------------------------------------
// Launch
// ---------------------------------------------------------------------------
extern "C" void kernel_launch(void* const* d_in, const int* in_sizes, int n_in,
                              void* d_out, int out_size) {
    int iSrc = 0, iEmb = 1, iW1 = 2, iB1 = 3, iW2 = 4, iB2 = 5;
    for (int i = 0; i < n_in; ++i) {
        int s = in_sizes[i];
        if      (s == B_ROWS * SRC_COLS)  iSrc = i;
        else if (s == VOCAB * EMB)        iEmb = i;
        else if (s == (NDEM + EMB) * NH)  iW1  = i;
        else if (s == NH)                 iB1  = i;
        else if (s == NH * 2)             iW2  = i;
        else if (s == 2)                  iB2  = i;
    }
    const float* src   = (const float*)d_in[iSrc];
    const float* embed = (const float*)d_in[iEmb];
    const float* W1    = (const float*)d_in[iW1];
    const float* b1    = (const float*)d_in[iB1];
    const float* W2    = (const float*)d_in[iW2];
    const float* b2    = (const float*)d_in[iB2];
    float* out = (float*)d_out;

    ew1_kernel<<<KPAD / 32, 512>>>(embed, W1);
    pool_kernel<<<NCTA, THREADS>>>(src);
    mlp_kernel<<<(B_ROWS + 255) / 256, 256>>>(src, W1, b1, W2, b2, out);
}